// round 2
// baseline (speedup 1.0000x reference)
#include <cuda_runtime.h>

// Projection: per row i of x[N,128]:
//   sq = sum(x_i^2); s = (sq-1)/(sq+1); out_i = [(1-s)*x_i, s]  -> out[N,129]
// with (1-s) = 2/(1+sq).
//
// Strategy: HBM-bound streaming. The output row stride (129 floats = 516B)
// makes direct per-row stores misaligned (5 L2 sectors per 128B transaction).
// Instead each block of 8 rows stages its contiguous 1032-float (4128B,
// 16B-aligned) output region in shared memory and streams it out with fully
// aligned float4 stores.

#define D 128
#define ROWS_PER_BLOCK 8
#define THREADS 256
#define OUT_FLOATS (ROWS_PER_BLOCK * (D + 1))   // 1032
#define OUT_VEC4   (OUT_FLOATS / 4)             // 258

__global__ void __launch_bounds__(THREADS) projection_kernel(
    const float4* __restrict__ x4, float* __restrict__ out, int n_rows)
{
    __shared__ __align__(16) float sout[OUT_FLOATS];

    const int t    = threadIdx.x;
    const int warp = t >> 5;        // row within block (warp == row)
    const int lane = t & 31;
    const long long block_row0 = (long long)blockIdx.x * ROWS_PER_BLOCK;

    // Aligned vector load: thread t covers row `warp`, cols [4*lane, 4*lane+4)
    const float4 v = x4[block_row0 * (D / 4) + t];

    float sq = v.x * v.x + v.y * v.y + v.z * v.z + v.w * v.w;
    #pragma unroll
    for (int off = 16; off > 0; off >>= 1)
        sq += __shfl_xor_sync(0xFFFFFFFFu, sq, off);

    const float inv   = 1.0f / (1.0f + sq);
    const float scale = 2.0f * inv;        // = 1 - s
    const float s     = (sq - 1.0f) * inv;

    // Stage into smem in exact output layout
    const int base = warp * (D + 1) + 4 * lane;
    sout[base + 0] = scale * v.x;
    sout[base + 1] = scale * v.y;
    sout[base + 2] = scale * v.z;
    sout[base + 3] = scale * v.w;
    if (lane == 0) sout[warp * (D + 1) + D] = s;

    __syncthreads();

    // Stream the contiguous, 16B-aligned block output region
    float4* __restrict__ o4 = (float4*)(out + block_row0 * (D + 1));
    const float4* __restrict__ s4 = (const float4*)sout;
    #pragma unroll
    for (int j = t; j < OUT_VEC4; j += THREADS)
        o4[j] = s4[j];
}

extern "C" void kernel_launch(void* const* d_in, const int* in_sizes, int n_in,
                              void* d_out, int out_size)
{
    const float4* x4 = (const float4*)d_in[0];
    float* out = (float*)d_out;
    const int n_rows = in_sizes[0] / D;                   // 1048576
    const int blocks = n_rows / ROWS_PER_BLOCK;           // exact: 131072
    projection_kernel<<<blocks, THREADS>>>(x4, out, n_rows);
}

// round 3
// speedup vs baseline: 1.1668x; 1.1668x over previous
#include <cuda_runtime.h>

// Projection: per row i of x[N,128]:
//   sq = sum(x_i^2); s = (sq-1)/(sq+1); out_i = [(1-s)*x_i, s]  -> out[N,129]
// with (1-s) = 2/(1+sq).
//
// HBM-bound streaming. R1 evidence: misaligned 516B-stride row stores merge
// fully in L2 (measured DRAM traffic == payload), so keep the scalar
// stride-32 coalesced pattern and instead raise per-thread MLP: each warp
// handles 4 rows, all 16 loads front-batched (64B in flight per thread).

#define D 128
#define THREADS 256
#define WARPS (THREADS / 32)
#define ROWS_PER_WARP 4
#define ROWS_PER_BLOCK (WARPS * ROWS_PER_WARP)   // 32

__global__ void __launch_bounds__(THREADS) projection_kernel(
    const float* __restrict__ x, float* __restrict__ out, int n_rows)
{
    const int warp = threadIdx.x >> 5;
    const int lane = threadIdx.x & 31;
    const long long row0 = (long long)blockIdx.x * ROWS_PER_BLOCK
                         + (long long)warp * ROWS_PER_WARP;

    const float* __restrict__ xr = x + row0 * D + lane;

    // Front-batched, fully coalesced streaming loads: 16 x LDG.32 (MLP=16)
    float v[ROWS_PER_WARP][4];
    #pragma unroll
    for (int r = 0; r < ROWS_PER_WARP; r++)
        #pragma unroll
        for (int c = 0; c < 4; c++)
            v[r][c] = __ldcs(xr + r * D + c * 32);

    float sq[ROWS_PER_WARP];
    #pragma unroll
    for (int r = 0; r < ROWS_PER_WARP; r++)
        sq[r] = v[r][0] * v[r][0] + v[r][1] * v[r][1]
              + v[r][2] * v[r][2] + v[r][3] * v[r][3];

    // Interleaved warp reductions (independent shuffle chains)
    #pragma unroll
    for (int off = 16; off > 0; off >>= 1)
        #pragma unroll
        for (int r = 0; r < ROWS_PER_WARP; r++)
            sq[r] += __shfl_xor_sync(0xFFFFFFFFu, sq[r], off);

    #pragma unroll
    for (int r = 0; r < ROWS_PER_WARP; r++) {
        const float inv   = 1.0f / (1.0f + sq[r]);
        const float scale = 2.0f * inv;        // = 1 - s
        const float s     = (sq[r] - 1.0f) * inv;

        float* __restrict__ orow = out + (row0 + r) * (D + 1);
        #pragma unroll
        for (int c = 0; c < 4; c++)
            orow[lane + c * 32] = scale * v[r][c];
        if (lane == 0) orow[D] = s;
    }
}

extern "C" void kernel_launch(void* const* d_in, const int* in_sizes, int n_in,
                              void* d_out, int out_size)
{
    const float* x = (const float*)d_in[0];
    float* out = (float*)d_out;
    const int n_rows = in_sizes[0] / D;                    // 1048576
    const int blocks = n_rows / ROWS_PER_BLOCK;            // exact: 32768
    projection_kernel<<<blocks, THREADS>>>(x, out, n_rows);
}